// round 9
// baseline (speedup 1.0000x reference)
#include <cuda_runtime.h>
#include <cuda_fp16.h>
#include <cstdint>
#include <cstring>

// Problem constants (fixed by the reference)
#define NN      100000
#define D_IN    256
#define D_OUT   128
#define NNZ_X   3200000
#define NNZ_A   3200000
#define INV_KEEP 1.1111112f   // float32(1/0.9), matching JAX

#define CAP     96            // bucket capacity per row; P(Poisson(32) > 96) ~ 1e-20

// Grid partitioning
#define SCAT_BLKS   (NNZ_X / 4 / 256)      // 3125 blocks for 4-nnz/thread scatter
#define WCONV_BLKS  64                     // 16384 half2 / 256
#define SPMM1_BLKS  (NN / 16)              // 6250 blocks, 16 rows per block
#define P1_BLKS     (SCAT_BLKS + WCONV_BLKS)
#define P2_BLKS     (SPMM1_BLKS + SCAT_BLKS)

// ---------------------------------------------------------------------------
// Static scratch (no allocations allowed). Zero-initialized at module load;
// fill counters are self-resetting (consumer writes 0 for the next replay).
// ---------------------------------------------------------------------------
__device__ __half g_h[(size_t)NN * D_OUT];          // 25.6 MB  H = X@W (fp16)
__device__ __half g_w16[D_IN * D_OUT];              // 64 KB    W in fp16
__device__ int    g_fill[2 * NN];                   // fillX | fillA
__device__ int2   g_bktX[(size_t)NN * CAP];         // 76.8 MB (col, val-bits)
__device__ int2   g_bktA[(size_t)NN * CAP];         // 76.8 MB

// bit-cast helpers
__device__ __forceinline__ uint32_t h2_to_u32(half2 h) {
    uint32_t u; memcpy(&u, &h, 4); return u;
}
__device__ __forceinline__ half2 u32_to_h2(uint32_t u) {
    half2 h; memcpy(&h, &u, 4); return h;
}

// ---------------------------------------------------------------------------
// threefry2x32, key = seed(42), partitionable mode: in = (0, i), out = o0^o1
// ---------------------------------------------------------------------------
__device__ __forceinline__ uint32_t rotl32(uint32_t v, int d) {
    return (v << d) | (v >> (32 - d));
}

__device__ __forceinline__ uint32_t threefry_bits_k42(uint32_t idx) {
    const uint32_t ks1 = 42u;
    const uint32_t ks2 = 42u ^ 0x1BD11BDAu;
    uint32_t x0 = 0u;
    uint32_t x1 = idx + ks1;
#define TF_ROUND(r) { x0 += x1; x1 = rotl32(x1, r); x1 ^= x0; }
    TF_ROUND(13) TF_ROUND(15) TF_ROUND(26) TF_ROUND(6)
    x0 += ks1; x1 += ks2 + 1u;
    TF_ROUND(17) TF_ROUND(29) TF_ROUND(16) TF_ROUND(24)
    x0 += ks2; x1 += 0u + 2u;
    TF_ROUND(13) TF_ROUND(15) TF_ROUND(26) TF_ROUND(6)
    x0 += 0u; x1 += ks1 + 3u;
    TF_ROUND(17) TF_ROUND(29) TF_ROUND(16) TF_ROUND(24)
    x0 += ks1; x1 += ks2 + 4u;
    TF_ROUND(13) TF_ROUND(15) TF_ROUND(26) TF_ROUND(6)
    x0 += ks2; x1 += 0u + 5u;
#undef TF_ROUND
    return x0 ^ x1;
}

__device__ __forceinline__ float bits_to_uniform(uint32_t bits) {
    return __uint_as_float((bits >> 9) | 0x3f800000u) - 1.0f;
}

// ---------------------------------------------------------------------------
// Phase 1: scatterX (with dropout) || W fp32->fp16 conversion
// ---------------------------------------------------------------------------
__global__ void k_phase1(const int* __restrict__ x_rows,
                         const int* __restrict__ x_cols,
                         const float* __restrict__ x_vals,
                         const float* __restrict__ W) {
    int b = blockIdx.x;
    if (b < SCAT_BLKS) {
        int i = (b * 256 + threadIdx.x) * 4;
        int4   r4 = __ldcs((const int4*)(x_rows + i));
        int4   c4 = __ldcs((const int4*)(x_cols + i));
        float4 v4 = __ldcs((const float4*)(x_vals + i));
        #pragma unroll
        for (int k = 0; k < 4; k++) {
            int   r = (&r4.x)[k];
            int   c = (&c4.x)[k];
            float v = (&v4.x)[k];
            uint32_t bits = threefry_bits_k42((uint32_t)(i + k));
            float u = bits_to_uniform(bits);
            if (0.9f + u < 1.0f) continue;     // dropped, skip entirely
            int slot = atomicAdd(g_fill + r, 1);
            if (slot < CAP)
                g_bktX[(size_t)r * CAP + slot] =
                    make_int2(c, __float_as_int(v * INV_KEEP));
        }
    } else {
        int j = (b - SCAT_BLKS) * 256 + threadIdx.x;   // half2 index < 16384
        float2 f = __ldg((const float2*)W + j);
        ((half2*)g_w16)[j] = __floats2half2_rn(f.x, f.y);
    }
}

// ---------------------------------------------------------------------------
// fma of 8 halves (uint4) scaled by v into 8-float accumulator
// ---------------------------------------------------------------------------
__device__ __forceinline__ void fma_h16(float4& a0, float4& a1, float v, uint4 q) {
    float2 f0 = __half22float2(u32_to_h2(q.x));
    float2 f1 = __half22float2(u32_to_h2(q.y));
    float2 f2 = __half22float2(u32_to_h2(q.z));
    float2 f3 = __half22float2(u32_to_h2(q.w));
    a0.x = fmaf(v, f0.x, a0.x); a0.y = fmaf(v, f0.y, a0.y);
    a0.z = fmaf(v, f1.x, a0.z); a0.w = fmaf(v, f1.y, a0.w);
    a1.x = fmaf(v, f2.x, a1.x); a1.y = fmaf(v, f2.y, a1.y);
    a1.z = fmaf(v, f3.x, a1.z); a1.w = fmaf(v, f3.y, a1.w);
}

// Read row count (one lane per row), broadcast to half-warp, reset for next replay.
__device__ __forceinline__ int load_reset_fill(int* cnt, int row, int lane, int sub) {
    int n = 0;
    if ((lane & 15) == 0) {
        n = cnt[row];
        cnt[row] = 0;                      // self-reset for next graph replay
    }
    n = __shfl_sync(0xffffffffu, n, sub << 4);
    return n > CAP ? CAP : n;
}

// ---------------------------------------------------------------------------
// Phase 2: SpMM1 (H = X @ W16, 2 rows/warp) || scatterA
// ---------------------------------------------------------------------------
__global__ void k_phase2(const int* __restrict__ a_rows,
                         const int* __restrict__ a_cols,
                         const float* __restrict__ a_vals) {
    int b = blockIdx.x;
    if (b < SPMM1_BLKS) {
        int lane = threadIdx.x & 31;
        int sub = lane >> 4;
        int sl  = lane & 15;
        int row = b * 16 + (threadIdx.x >> 5) * 2 + sub;
        int n = load_reset_fill(g_fill, row, lane, sub);
        const int2*  bkt = g_bktX + (size_t)row * CAP;
        const int4*  b4  = (const int4*)bkt;
        const uint4* W4  = (const uint4*)g_w16;
        float4 a0 = make_float4(0.f, 0.f, 0.f, 0.f);
        float4 a1 = make_float4(0.f, 0.f, 0.f, 0.f);
        int j = 0;
        for (; j + 3 < n; j += 4) {
            int4 pA = __ldcs(b4 + (j >> 1));
            int4 pB = __ldcs(b4 + (j >> 1) + 1);
            uint4 q0 = __ldg(W4 + (size_t)pA.x * 16 + sl);
            uint4 q1 = __ldg(W4 + (size_t)pA.z * 16 + sl);
            uint4 q2 = __ldg(W4 + (size_t)pB.x * 16 + sl);
            uint4 q3 = __ldg(W4 + (size_t)pB.z * 16 + sl);
            fma_h16(a0, a1, __int_as_float(pA.y), q0);
            fma_h16(a0, a1, __int_as_float(pA.w), q1);
            fma_h16(a0, a1, __int_as_float(pB.y), q2);
            fma_h16(a0, a1, __int_as_float(pB.w), q3);
        }
        for (; j < n; j++) {
            int2 cv = __ldcs(bkt + j);
            uint4 q = __ldg(W4 + (size_t)cv.x * 16 + sl);
            fma_h16(a0, a1, __int_as_float(cv.y), q);
        }
        uint4 packed;
        packed.x = h2_to_u32(__floats2half2_rn(a0.x, a0.y));
        packed.y = h2_to_u32(__floats2half2_rn(a0.z, a0.w));
        packed.z = h2_to_u32(__floats2half2_rn(a1.x, a1.y));
        packed.w = h2_to_u32(__floats2half2_rn(a1.z, a1.w));
        ((uint4*)g_h)[(size_t)row * 16 + sl] = packed;
    } else {
        int i = ((b - SPMM1_BLKS) * 256 + threadIdx.x) * 4;
        int4   r4 = __ldcs((const int4*)(a_rows + i));
        int4   c4 = __ldcs((const int4*)(a_cols + i));
        float4 v4 = __ldcs((const float4*)(a_vals + i));
        #pragma unroll
        for (int k = 0; k < 4; k++) {
            int   r = (&r4.x)[k];
            int   c = (&c4.x)[k];
            float v = (&v4.x)[k];
            int slot = atomicAdd(g_fill + NN + r, 1);
            if (slot < CAP)
                g_bktA[(size_t)r * CAP + slot] = make_int2(c, __float_as_int(v));
        }
    }
}

// ---------------------------------------------------------------------------
// Phase 3: SpMM2 + ReLU: out(fp32) = relu(A @ H).  2 rows/warp, unroll 8.
// ---------------------------------------------------------------------------
__global__ void k_spmm2(float* __restrict__ out) {
    int gw = (blockIdx.x * blockDim.x + threadIdx.x) >> 5;
    int lane = threadIdx.x & 31;
    int sub = lane >> 4;
    int sl  = lane & 15;
    int row = gw * 2 + sub;
    if (row >= NN) return;
    int n = load_reset_fill(g_fill + NN, row, lane, sub);
    const int2*  bkt = g_bktA + (size_t)row * CAP;
    const int4*  b4  = (const int4*)bkt;
    const uint4* H4  = (const uint4*)g_h;
    float4 a0 = make_float4(0.f, 0.f, 0.f, 0.f);
    float4 a1 = make_float4(0.f, 0.f, 0.f, 0.f);
    int j = 0;
    for (; j + 7 < n; j += 8) {
        int4 pA = __ldcs(b4 + (j >> 1));
        int4 pB = __ldcs(b4 + (j >> 1) + 1);
        int4 pC = __ldcs(b4 + (j >> 1) + 2);
        int4 pD = __ldcs(b4 + (j >> 1) + 3);
        uint4 q0 = __ldg(H4 + (size_t)pA.x * 16 + sl);
        uint4 q1 = __ldg(H4 + (size_t)pA.z * 16 + sl);
        uint4 q2 = __ldg(H4 + (size_t)pB.x * 16 + sl);
        uint4 q3 = __ldg(H4 + (size_t)pB.z * 16 + sl);
        uint4 q4 = __ldg(H4 + (size_t)pC.x * 16 + sl);
        uint4 q5 = __ldg(H4 + (size_t)pC.z * 16 + sl);
        uint4 q6 = __ldg(H4 + (size_t)pD.x * 16 + sl);
        uint4 q7 = __ldg(H4 + (size_t)pD.z * 16 + sl);
        fma_h16(a0, a1, __int_as_float(pA.y), q0);
        fma_h16(a0, a1, __int_as_float(pA.w), q1);
        fma_h16(a0, a1, __int_as_float(pB.y), q2);
        fma_h16(a0, a1, __int_as_float(pB.w), q3);
        fma_h16(a0, a1, __int_as_float(pC.y), q4);
        fma_h16(a0, a1, __int_as_float(pC.w), q5);
        fma_h16(a0, a1, __int_as_float(pD.y), q6);
        fma_h16(a0, a1, __int_as_float(pD.w), q7);
    }
    for (; j < n; j++) {
        int2 cv = __ldcs(bkt + j);
        uint4 q = __ldg(H4 + (size_t)cv.x * 16 + sl);
        fma_h16(a0, a1, __int_as_float(cv.y), q);
    }
    a0.x = fmaxf(a0.x, 0.f); a0.y = fmaxf(a0.y, 0.f);
    a0.z = fmaxf(a0.z, 0.f); a0.w = fmaxf(a0.w, 0.f);
    a1.x = fmaxf(a1.x, 0.f); a1.y = fmaxf(a1.y, 0.f);
    a1.z = fmaxf(a1.z, 0.f); a1.w = fmaxf(a1.w, 0.f);
    float4* o4 = (float4*)out + (size_t)row * 32 + sl * 2;
    o4[0] = a0;
    o4[1] = a1;
}

// ---------------------------------------------------------------------------
// Launch: 3 kernels total (independent work packed into shared launches)
// ---------------------------------------------------------------------------
extern "C" void kernel_launch(void* const* d_in, const int* in_sizes, int n_in,
                              void* d_out, int out_size) {
    const int*   x_rows   = (const int*)  d_in[0];
    const int*   x_cols   = (const int*)  d_in[1];
    const float* x_vals   = (const float*)d_in[2];
    const int*   adj_rows = (const int*)  d_in[3];
    const int*   adj_cols = (const int*)  d_in[4];
    const float* adj_vals = (const float*)d_in[5];
    const float* W        = (const float*)d_in[6];
    float* out = (float*)d_out;

    // Phase 1: scatterX (dropout fused) || W -> fp16
    k_phase1<<<P1_BLKS, 256>>>(x_rows, x_cols, x_vals, W);

    // Phase 2: spmm1 (H = X @ W16) || scatterA  (independent, one launch)
    k_phase2<<<P2_BLKS, 256>>>(adj_rows, adj_cols, adj_vals);

    // Phase 3: spmm2 + ReLU
    {
        long long threads = (long long)(NN / 2) * 32;
        int blocks = (int)((threads + 255) / 256);
        k_spmm2<<<blocks, 256>>>(out);
    }
}

// round 10
// speedup vs baseline: 1.8692x; 1.8692x over previous
#include <cuda_runtime.h>
#include <cuda_fp16.h>
#include <cstdint>
#include <cstring>

// Problem constants (fixed by the reference)
#define NN      100000
#define D_IN    256
#define D_OUT   128
#define NNZ_X   3200000
#define NNZ_A   3200000
#define INV_KEEP 1.1111112f   // float32(1/0.9), matching JAX

#define CAP     96            // bucket capacity per row; P(Poisson(32) > 96) ~ 1e-20

// ---------------------------------------------------------------------------
// Static scratch (no allocations allowed). +8 entry tail pad: the pipelined
// gather loops prefetch up to 2 entries past a row's CAP region.
// ---------------------------------------------------------------------------
__device__ __half g_h[(size_t)NN * D_OUT];          // 25.6 MB  H = X@W (fp16)
__device__ __half g_w16[D_IN * D_OUT];              // 64 KB    W in fp16
__device__ int    g_fill[2 * NN];                   // fillX | fillA
__device__ int2   g_bktX[(size_t)NN * CAP + 8];     // 76.8 MB (col, val-bits)
__device__ int2   g_bktA[(size_t)NN * CAP + 8];     // 76.8 MB

// bit-cast helpers
__device__ __forceinline__ uint32_t h2_to_u32(half2 h) {
    uint32_t u; memcpy(&u, &h, 4); return u;
}
__device__ __forceinline__ half2 u32_to_h2(uint32_t u) {
    half2 h; memcpy(&h, &u, 4); return h;
}

// ---------------------------------------------------------------------------
// threefry2x32, key = seed(42), partitionable mode: in = (0, i), out = o0^o1
// ---------------------------------------------------------------------------
__device__ __forceinline__ uint32_t rotl32(uint32_t v, int d) {
    return (v << d) | (v >> (32 - d));
}

__device__ __forceinline__ uint32_t threefry_bits_k42(uint32_t idx) {
    const uint32_t ks1 = 42u;
    const uint32_t ks2 = 42u ^ 0x1BD11BDAu;
    uint32_t x0 = 0u;
    uint32_t x1 = idx + ks1;
#define TF_ROUND(r) { x0 += x1; x1 = rotl32(x1, r); x1 ^= x0; }
    TF_ROUND(13) TF_ROUND(15) TF_ROUND(26) TF_ROUND(6)
    x0 += ks1; x1 += ks2 + 1u;
    TF_ROUND(17) TF_ROUND(29) TF_ROUND(16) TF_ROUND(24)
    x0 += ks2; x1 += 0u + 2u;
    TF_ROUND(13) TF_ROUND(15) TF_ROUND(26) TF_ROUND(6)
    x0 += 0u; x1 += ks1 + 3u;
    TF_ROUND(17) TF_ROUND(29) TF_ROUND(16) TF_ROUND(24)
    x0 += ks1; x1 += ks2 + 4u;
    TF_ROUND(13) TF_ROUND(15) TF_ROUND(26) TF_ROUND(6)
    x0 += ks2; x1 += 0u + 5u;
#undef TF_ROUND
    return x0 ^ x1;
}

__device__ __forceinline__ float bits_to_uniform(uint32_t bits) {
    return __uint_as_float((bits >> 9) | 0x3f800000u) - 1.0f;
}

// ---------------------------------------------------------------------------
// Prep: zero fill counters (2*NN ints = 50000 int4) + convert W to fp16
// ---------------------------------------------------------------------------
#define FILL_I4  (2 * NN / 4)                 // 50000
#define WCONV    (D_IN * D_OUT / 2)           // 16384 half2 outputs

__global__ void k_prep(const float* __restrict__ W) {
    int i = blockIdx.x * blockDim.x + threadIdx.x;
    if (i < FILL_I4) {
        ((int4*)g_fill)[i] = make_int4(0, 0, 0, 0);
    } else if (i < FILL_I4 + WCONV) {
        int j = i - FILL_I4;                   // half2 index
        float2 f = ((const float2*)W)[j];
        ((half2*)g_w16)[j] = __floats2half2_rn(f.x, f.y);
    }
}

// ---------------------------------------------------------------------------
// Scatter into row buckets, 4 nnz per thread (blockIdx.y: 0 = X w/ dropout, 1 = A)
// ---------------------------------------------------------------------------
__global__ void k_scatter_both(const int* __restrict__ x_rows,
                               const int* __restrict__ x_cols,
                               const float* __restrict__ x_vals,
                               const int* __restrict__ a_rows,
                               const int* __restrict__ a_cols,
                               const float* __restrict__ a_vals) {
    int t = blockIdx.x * blockDim.x + threadIdx.x;
    int i = t * 4;
    if (blockIdx.y == 0) {
        if (i >= NNZ_X) return;
        int4   r4 = __ldg((const int4*)(x_rows + i));
        int4   c4 = __ldg((const int4*)(x_cols + i));
        float4 v4 = __ldg((const float4*)(x_vals + i));
        #pragma unroll
        for (int k = 0; k < 4; k++) {
            int   r = (&r4.x)[k];
            int   c = (&c4.x)[k];
            float v = (&v4.x)[k];
            uint32_t bits = threefry_bits_k42((uint32_t)(i + k));
            float u = bits_to_uniform(bits);
            if (0.9f + u < 1.0f) continue;     // dropped, skip entirely
            int slot = atomicAdd(g_fill + r, 1);
            if (slot < CAP)
                g_bktX[(size_t)r * CAP + slot] =
                    make_int2(c, __float_as_int(v * INV_KEEP));
        }
    } else {
        if (i >= NNZ_A) return;
        int4   r4 = __ldg((const int4*)(a_rows + i));
        int4   c4 = __ldg((const int4*)(a_cols + i));
        float4 v4 = __ldg((const float4*)(a_vals + i));
        #pragma unroll
        for (int k = 0; k < 4; k++) {
            int   r = (&r4.x)[k];
            int   c = (&c4.x)[k];
            float v = (&v4.x)[k];
            int slot = atomicAdd(g_fill + NN + r, 1);
            if (slot < CAP)
                g_bktA[(size_t)r * CAP + slot] = make_int2(c, __float_as_int(v));
        }
    }
}

// ---------------------------------------------------------------------------
// fma of 8 halves (uint4) scaled by v into 8-float accumulator
// ---------------------------------------------------------------------------
__device__ __forceinline__ void fma_h16(float4& a0, float4& a1, float v, uint4 q) {
    float2 f0 = __half22float2(u32_to_h2(q.x));
    float2 f1 = __half22float2(u32_to_h2(q.y));
    float2 f2 = __half22float2(u32_to_h2(q.z));
    float2 f3 = __half22float2(u32_to_h2(q.w));
    a0.x = fmaf(v, f0.x, a0.x); a0.y = fmaf(v, f0.y, a0.y);
    a0.z = fmaf(v, f1.x, a0.z); a0.w = fmaf(v, f1.y, a0.w);
    a1.x = fmaf(v, f2.x, a1.x); a1.y = fmaf(v, f2.y, a1.y);
    a1.z = fmaf(v, f3.x, a1.z); a1.w = fmaf(v, f3.y, a1.w);
}

// ---------------------------------------------------------------------------
// SpMM1: H(fp16) = X @ W16.  2 rows/warp, 16 lanes/row, lane owns 8 cols.
// Bucket reads pipelined one unrolled iteration ahead (breaks bkt->W chain).
// ---------------------------------------------------------------------------
__global__ void k_spmm1(__half* __restrict__ H) {
    int gw = (blockIdx.x * blockDim.x + threadIdx.x) >> 5;   // warp id
    int lane = threadIdx.x & 31;
    int sub = lane >> 4;              // 0/1: which row of the pair
    int sl  = lane & 15;              // lane-within-row, owns cols [sl*8, sl*8+8)
    int row = gw * 2 + sub;
    if (row >= NN) return;
    int n = __ldg(g_fill + row);
    if (n > CAP) n = CAP;
    const int2*  bkt = g_bktX + (size_t)row * CAP;
    const int4*  b4  = (const int4*)bkt;                     // pair of entries
    const uint4* W4  = (const uint4*)g_w16;                  // 8 halves per uint4
    float4 a0 = make_float4(0.f, 0.f, 0.f, 0.f);
    float4 a1 = make_float4(0.f, 0.f, 0.f, 0.f);
    int j = 0;
    if (j + 3 < n) {
        // pipelined unroll-4: prefetch next pair-of-pairs before using current
        int4 pA = __ldg(b4);
        int4 pB = __ldg(b4 + 1);
        for (; j + 3 < n; j += 4) {
            int kn = (j >> 1) + 2;
            int4 pA2 = __ldg(b4 + kn);       // may overread into pad: unused then
            int4 pB2 = __ldg(b4 + kn + 1);
            uint4 q0 = __ldg(W4 + (size_t)pA.x * 16 + sl);
            uint4 q1 = __ldg(W4 + (size_t)pA.z * 16 + sl);
            uint4 q2 = __ldg(W4 + (size_t)pB.x * 16 + sl);
            uint4 q3 = __ldg(W4 + (size_t)pB.z * 16 + sl);
            fma_h16(a0, a1, __int_as_float(pA.y), q0);
            fma_h16(a0, a1, __int_as_float(pA.w), q1);
            fma_h16(a0, a1, __int_as_float(pB.y), q2);
            fma_h16(a0, a1, __int_as_float(pB.w), q3);
            pA = pA2; pB = pB2;
        }
    }
    for (; j < n; j++) {
        int2 cv = __ldg(bkt + j);
        uint4 q = __ldg(W4 + (size_t)cv.x * 16 + sl);
        fma_h16(a0, a1, __int_as_float(cv.y), q);
    }
    uint4 packed;
    packed.x = h2_to_u32(__floats2half2_rn(a0.x, a0.y));
    packed.y = h2_to_u32(__floats2half2_rn(a0.z, a0.w));
    packed.z = h2_to_u32(__floats2half2_rn(a1.x, a1.y));
    packed.w = h2_to_u32(__floats2half2_rn(a1.z, a1.w));
    ((uint4*)H)[(size_t)row * 16 + sl] = packed;
}

// ---------------------------------------------------------------------------
// SpMM2 + ReLU: out(fp32) = relu(A @ H).  2 rows/warp, pipelined unroll 4.
// ---------------------------------------------------------------------------
__global__ void k_spmm2(const __half* __restrict__ H, float* __restrict__ out) {
    int gw = (blockIdx.x * blockDim.x + threadIdx.x) >> 5;
    int lane = threadIdx.x & 31;
    int sub = lane >> 4;
    int sl  = lane & 15;
    int row = gw * 2 + sub;
    if (row >= NN) return;
    int n = __ldg(g_fill + NN + row);
    if (n > CAP) n = CAP;
    const int2*  bkt = g_bktA + (size_t)row * CAP;
    const int4*  b4  = (const int4*)bkt;
    const uint4* H4  = (const uint4*)H;
    float4 a0 = make_float4(0.f, 0.f, 0.f, 0.f);
    float4 a1 = make_float4(0.f, 0.f, 0.f, 0.f);
    int j = 0;
    if (j + 3 < n) {
        int4 pA = __ldg(b4);
        int4 pB = __ldg(b4 + 1);
        for (; j + 3 < n; j += 4) {
            int kn = (j >> 1) + 2;
            int4 pA2 = __ldg(b4 + kn);       // prefetch next iteration's entries
            int4 pB2 = __ldg(b4 + kn + 1);
            uint4 q0 = __ldg(H4 + (size_t)pA.x * 16 + sl);
            uint4 q1 = __ldg(H4 + (size_t)pA.z * 16 + sl);
            uint4 q2 = __ldg(H4 + (size_t)pB.x * 16 + sl);
            uint4 q3 = __ldg(H4 + (size_t)pB.z * 16 + sl);
            fma_h16(a0, a1, __int_as_float(pA.y), q0);
            fma_h16(a0, a1, __int_as_float(pA.w), q1);
            fma_h16(a0, a1, __int_as_float(pB.y), q2);
            fma_h16(a0, a1, __int_as_float(pB.w), q3);
            pA = pA2; pB = pB2;
        }
    }
    for (; j < n; j++) {
        int2 cv = __ldg(bkt + j);
        uint4 q = __ldg(H4 + (size_t)cv.x * 16 + sl);
        fma_h16(a0, a1, __int_as_float(cv.y), q);
    }
    a0.x = fmaxf(a0.x, 0.f); a0.y = fmaxf(a0.y, 0.f);
    a0.z = fmaxf(a0.z, 0.f); a0.w = fmaxf(a0.w, 0.f);
    a1.x = fmaxf(a1.x, 0.f); a1.y = fmaxf(a1.y, 0.f);
    a1.z = fmaxf(a1.z, 0.f); a1.w = fmaxf(a1.w, 0.f);
    float4* o4 = (float4*)out + (size_t)row * 32 + sl * 2;   // 8 floats = 2x float4
    o4[0] = a0;
    o4[1] = a1;
}

// ---------------------------------------------------------------------------
// Launch: 4 kernels total
// ---------------------------------------------------------------------------
extern "C" void kernel_launch(void* const* d_in, const int* in_sizes, int n_in,
                              void* d_out, int out_size) {
    const int*   x_rows   = (const int*)  d_in[0];
    const int*   x_cols   = (const int*)  d_in[1];
    const float* x_vals   = (const float*)d_in[2];
    const int*   adj_rows = (const int*)  d_in[3];
    const int*   adj_cols = (const int*)  d_in[4];
    const float* adj_vals = (const float*)d_in[5];
    const float* W        = (const float*)d_in[6];
    float* out = (float*)d_out;

    __half* h_ptr;  cudaGetSymbolAddress((void**)&h_ptr, g_h);

    // 1. zero fill counters + convert W to fp16
    {
        int work = FILL_I4 + WCONV;
        k_prep<<<(work + 255) / 256, 256>>>(W);
    }

    // 2. scatter both matrices into row buckets (4 nnz/thread, X and A via grid.y)
    {
        dim3 g((NNZ_X / 4 + 255) / 256, 2);
        k_scatter_both<<<g, 256>>>(x_rows, x_cols, x_vals,
                                   adj_rows, adj_cols, adj_vals);
    }

    // 3. SpMM1: H(fp16) = X @ W16   (2 rows per warp)
    {
        long long threads = (long long)(NN / 2) * 32;
        int blocks = (int)((threads + 255) / 256);
        k_spmm1<<<blocks, 256>>>(h_ptr);
    }

    // 4. SpMM2 + ReLU: out = relu(A @ H)   (2 rows per warp)
    {
        long long threads = (long long)(NN / 2) * 32;
        int blocks = (int)((threads + 255) / 256);
        k_spmm2<<<blocks, 256>>>(h_ptr, out);
    }
}

// round 12
// speedup vs baseline: 1.9079x; 1.0207x over previous
#include <cuda_runtime.h>
#include <cuda_fp16.h>
#include <cstdint>
#include <cstring>

// Problem constants (fixed by the reference)
#define NN      100000
#define D_IN    256
#define D_OUT   128
#define NNZ_X   3200000
#define NNZ_A   3200000
#define INV_KEEP 1.1111112f   // float32(1/0.9), matching JAX

#define CAP     96            // bucket capacity per row; P(Poisson(32) > 96) ~ 1e-20

#define SCAT_BLKS   (NNZ_X / 4 / 256)      // 3125 blocks, 4 nnz/thread
#define SPMM1_BLKS  (NN / 16)              // 6250 blocks, 16 rows per block (8 warps x 2)

// ---------------------------------------------------------------------------
// Static scratch (no allocations allowed). +8 entry tail pad: the pipelined
// gather loops prefetch up to 2 entries past a row's CAP region.
// ---------------------------------------------------------------------------
__device__ __half g_h[(size_t)NN * D_OUT];          // 25.6 MB  H = X@W (fp16)
__device__ __half g_w16[D_IN * D_OUT];              // 64 KB    W in fp16
__device__ int    g_fill[2 * NN];                   // fillX | fillA
__device__ int2   g_bktX[(size_t)NN * CAP + 8];     // 76.8 MB (col, val-bits)
__device__ int2   g_bktA[(size_t)NN * CAP + 8];     // 76.8 MB

// bit-cast helpers
__device__ __forceinline__ uint32_t h2_to_u32(half2 h) {
    uint32_t u; memcpy(&u, &h, 4); return u;
}
__device__ __forceinline__ half2 u32_to_h2(uint32_t u) {
    half2 h; memcpy(&h, &u, 4); return h;
}

// ---------------------------------------------------------------------------
// threefry2x32, key = seed(42), partitionable mode: in = (0, i), out = o0^o1
// ---------------------------------------------------------------------------
__device__ __forceinline__ uint32_t rotl32(uint32_t v, int d) {
    return (v << d) | (v >> (32 - d));
}

__device__ __forceinline__ uint32_t threefry_bits_k42(uint32_t idx) {
    const uint32_t ks1 = 42u;
    const uint32_t ks2 = 42u ^ 0x1BD11BDAu;
    uint32_t x0 = 0u;
    uint32_t x1 = idx + ks1;
#define TF_ROUND(r) { x0 += x1; x1 = rotl32(x1, r); x1 ^= x0; }
    TF_ROUND(13) TF_ROUND(15) TF_ROUND(26) TF_ROUND(6)
    x0 += ks1; x1 += ks2 + 1u;
    TF_ROUND(17) TF_ROUND(29) TF_ROUND(16) TF_ROUND(24)
    x0 += ks2; x1 += 0u + 2u;
    TF_ROUND(13) TF_ROUND(15) TF_ROUND(26) TF_ROUND(6)
    x0 += 0u; x1 += ks1 + 3u;
    TF_ROUND(17) TF_ROUND(29) TF_ROUND(16) TF_ROUND(24)
    x0 += ks1; x1 += ks2 + 4u;
    TF_ROUND(13) TF_ROUND(15) TF_ROUND(26) TF_ROUND(6)
    x0 += ks2; x1 += 0u + 5u;
#undef TF_ROUND
    return x0 ^ x1;
}

__device__ __forceinline__ float bits_to_uniform(uint32_t bits) {
    return __uint_as_float((bits >> 9) | 0x3f800000u) - 1.0f;
}

// ---------------------------------------------------------------------------
// Prep: zero fill counters (2*NN ints = 50000 int4) + convert W to fp16
// ---------------------------------------------------------------------------
#define FILL_I4  (2 * NN / 4)                 // 50000
#define WCONV    (D_IN * D_OUT / 2)           // 16384 half2 outputs

__global__ void k_prep(const float* __restrict__ W) {
    int i = blockIdx.x * blockDim.x + threadIdx.x;
    if (i < FILL_I4) {
        ((int4*)g_fill)[i] = make_int4(0, 0, 0, 0);
    } else if (i < FILL_I4 + WCONV) {
        int j = i - FILL_I4;                   // half2 index
        float2 f = ((const float2*)W)[j];
        ((half2*)g_w16)[j] = __floats2half2_rn(f.x, f.y);
    }
}

// ---------------------------------------------------------------------------
// Scatter X into row buckets, 4 nnz per thread, dropout fused
// ---------------------------------------------------------------------------
__global__ void k_scatter_x(const int* __restrict__ x_rows,
                            const int* __restrict__ x_cols,
                            const float* __restrict__ x_vals) {
    int i = (blockIdx.x * blockDim.x + threadIdx.x) * 4;
    if (i >= NNZ_X) return;
    int4   r4 = __ldg((const int4*)(x_rows + i));
    int4   c4 = __ldg((const int4*)(x_cols + i));
    float4 v4 = __ldg((const float4*)(x_vals + i));
    #pragma unroll
    for (int k = 0; k < 4; k++) {
        int   r = (&r4.x)[k];
        int   c = (&c4.x)[k];
        float v = (&v4.x)[k];
        uint32_t bits = threefry_bits_k42((uint32_t)(i + k));
        float u = bits_to_uniform(bits);
        if (0.9f + u < 1.0f) continue;     // dropped, skip entirely
        int slot = atomicAdd(g_fill + r, 1);
        if (slot < CAP)
            g_bktX[(size_t)r * CAP + slot] =
                make_int2(c, __float_as_int(v * INV_KEEP));
    }
}

// ---------------------------------------------------------------------------
// fma of 8 halves (uint4) scaled by v into 8-float accumulator
// ---------------------------------------------------------------------------
__device__ __forceinline__ void fma_h16(float4& a0, float4& a1, float v, uint4 q) {
    float2 f0 = __half22float2(u32_to_h2(q.x));
    float2 f1 = __half22float2(u32_to_h2(q.y));
    float2 f2 = __half22float2(u32_to_h2(q.z));
    float2 f3 = __half22float2(u32_to_h2(q.w));
    a0.x = fmaf(v, f0.x, a0.x); a0.y = fmaf(v, f0.y, a0.y);
    a0.z = fmaf(v, f1.x, a0.z); a0.w = fmaf(v, f1.y, a0.w);
    a1.x = fmaf(v, f2.x, a1.x); a1.y = fmaf(v, f2.y, a1.y);
    a1.z = fmaf(v, f3.x, a1.z); a1.w = fmaf(v, f3.y, a1.w);
}

// ---------------------------------------------------------------------------
// Fused launch: blocks [0, SPMM1_BLKS) run SpMM1 (H = X @ W16, 2 rows/warp,
// pipelined unroll-4); blocks [SPMM1_BLKS, +SCAT_BLKS) scatter A into buckets.
// The two halves touch disjoint data (bktX/W16/H vs COO-A/bktA/fillA).
// ---------------------------------------------------------------------------
__global__ void k_spmm1_scatter_a(const int* __restrict__ a_rows,
                                  const int* __restrict__ a_cols,
                                  const float* __restrict__ a_vals,
                                  __half* __restrict__ H) {
    int b = blockIdx.x;
    if (b < SPMM1_BLKS) {
        int lane = threadIdx.x & 31;
        int sub = lane >> 4;              // 0/1: which row of the pair
        int sl  = lane & 15;              // lane-within-row, owns cols [sl*8, sl*8+8)
        int row = b * 16 + (threadIdx.x >> 5) * 2 + sub;
        int n = __ldg(g_fill + row);
        if (n > CAP) n = CAP;
        const int2*  bkt = g_bktX + (size_t)row * CAP;
        const int4*  b4  = (const int4*)bkt;                 // pair of entries
        const uint4* W4  = (const uint4*)g_w16;              // 8 halves per uint4
        float4 a0 = make_float4(0.f, 0.f, 0.f, 0.f);
        float4 a1 = make_float4(0.f, 0.f, 0.f, 0.f);
        int j = 0;
        if (j + 3 < n) {
            int4 pA = __ldg(b4);
            int4 pB = __ldg(b4 + 1);
            for (; j + 3 < n; j += 4) {
                int kn = (j >> 1) + 2;
                int4 pA2 = __ldg(b4 + kn);   // may overread into pad: unused then
                int4 pB2 = __ldg(b4 + kn + 1);
                uint4 q0 = __ldg(W4 + (size_t)pA.x * 16 + sl);
                uint4 q1 = __ldg(W4 + (size_t)pA.z * 16 + sl);
                uint4 q2 = __ldg(W4 + (size_t)pB.x * 16 + sl);
                uint4 q3 = __ldg(W4 + (size_t)pB.z * 16 + sl);
                fma_h16(a0, a1, __int_as_float(pA.y), q0);
                fma_h16(a0, a1, __int_as_float(pA.w), q1);
                fma_h16(a0, a1, __int_as_float(pB.y), q2);
                fma_h16(a0, a1, __int_as_float(pB.w), q3);
                pA = pA2; pB = pB2;
            }
        }
        for (; j < n; j++) {
            int2 cv = __ldg(bkt + j);
            uint4 q = __ldg(W4 + (size_t)cv.x * 16 + sl);
            fma_h16(a0, a1, __int_as_float(cv.y), q);
        }
        uint4 packed;
        packed.x = h2_to_u32(__floats2half2_rn(a0.x, a0.y));
        packed.y = h2_to_u32(__floats2half2_rn(a0.z, a0.w));
        packed.z = h2_to_u32(__floats2half2_rn(a1.x, a1.y));
        packed.w = h2_to_u32(__floats2half2_rn(a1.z, a1.w));
        ((uint4*)H)[(size_t)row * 16 + sl] = packed;
    } else {
        int i = ((b - SPMM1_BLKS) * 256 + threadIdx.x) * 4;
        if (i >= NNZ_A) return;
        int4   r4 = __ldg((const int4*)(a_rows + i));
        int4   c4 = __ldg((const int4*)(a_cols + i));
        float4 v4 = __ldg((const float4*)(a_vals + i));
        #pragma unroll
        for (int k = 0; k < 4; k++) {
            int   r = (&r4.x)[k];
            int   c = (&c4.x)[k];
            float v = (&v4.x)[k];
            int slot = atomicAdd(g_fill + NN + r, 1);
            if (slot < CAP)
                g_bktA[(size_t)r * CAP + slot] = make_int2(c, __float_as_int(v));
        }
    }
}

// ---------------------------------------------------------------------------
// SpMM2 + ReLU: out(fp32) = relu(A @ H).  2 rows/warp, pipelined unroll 4.
// ---------------------------------------------------------------------------
__global__ void k_spmm2(const __half* __restrict__ H, float* __restrict__ out) {
    int gw = (blockIdx.x * blockDim.x + threadIdx.x) >> 5;
    int lane = threadIdx.x & 31;
    int sub = lane >> 4;
    int sl  = lane & 15;
    int row = gw * 2 + sub;
    if (row >= NN) return;
    int n = __ldg(g_fill + NN + row);
    if (n > CAP) n = CAP;
    const int2*  bkt = g_bktA + (size_t)row * CAP;
    const int4*  b4  = (const int4*)bkt;
    const uint4* H4  = (const uint4*)H;
    float4 a0 = make_float4(0.f, 0.f, 0.f, 0.f);
    float4 a1 = make_float4(0.f, 0.f, 0.f, 0.f);
    int j = 0;
    if (j + 3 < n) {
        int4 pA = __ldg(b4);
        int4 pB = __ldg(b4 + 1);
        for (; j + 3 < n; j += 4) {
            int kn = (j >> 1) + 2;
            int4 pA2 = __ldg(b4 + kn);       // prefetch next iteration's entries
            int4 pB2 = __ldg(b4 + kn + 1);
            uint4 q0 = __ldg(H4 + (size_t)pA.x * 16 + sl);
            uint4 q1 = __ldg(H4 + (size_t)pA.z * 16 + sl);
            uint4 q2 = __ldg(H4 + (size_t)pB.x * 16 + sl);
            uint4 q3 = __ldg(H4 + (size_t)pB.z * 16 + sl);
            fma_h16(a0, a1, __int_as_float(pA.y), q0);
            fma_h16(a0, a1, __int_as_float(pA.w), q1);
            fma_h16(a0, a1, __int_as_float(pB.y), q2);
            fma_h16(a0, a1, __int_as_float(pB.w), q3);
            pA = pA2; pB = pB2;
        }
    }
    for (; j < n; j++) {
        int2 cv = __ldg(bkt + j);
        uint4 q = __ldg(H4 + (size_t)cv.x * 16 + sl);
        fma_h16(a0, a1, __int_as_float(cv.y), q);
    }
    a0.x = fmaxf(a0.x, 0.f); a0.y = fmaxf(a0.y, 0.f);
    a0.z = fmaxf(a0.z, 0.f); a0.w = fmaxf(a0.w, 0.f);
    a1.x = fmaxf(a1.x, 0.f); a1.y = fmaxf(a1.y, 0.f);
    a1.z = fmaxf(a1.z, 0.f); a1.w = fmaxf(a1.w, 0.f);
    float4* o4 = (float4*)out + (size_t)row * 32 + sl * 2;   // 8 floats = 2x float4
    o4[0] = a0;
    o4[1] = a1;
}

// ---------------------------------------------------------------------------
// Launch: 4 kernels; scatterA hides under spmm1
// ---------------------------------------------------------------------------
extern "C" void kernel_launch(void* const* d_in, const int* in_sizes, int n_in,
                              void* d_out, int out_size) {
    const int*   x_rows   = (const int*)  d_in[0];
    const int*   x_cols   = (const int*)  d_in[1];
    const float* x_vals   = (const float*)d_in[2];
    const int*   adj_rows = (const int*)  d_in[3];
    const int*   adj_cols = (const int*)  d_in[4];
    const float* adj_vals = (const float*)d_in[5];
    const float* W        = (const float*)d_in[6];
    float* out = (float*)d_out;

    __half* h_ptr;  cudaGetSymbolAddress((void**)&h_ptr, g_h);

    // 1. zero fill counters + convert W to fp16
    {
        int work = FILL_I4 + WCONV;
        k_prep<<<(work + 255) / 256, 256>>>(W);
    }

    // 2. scatter X into row buckets (dropout fused)
    k_scatter_x<<<SCAT_BLKS, 256>>>(x_rows, x_cols, x_vals);

    // 3. fused: SpMM1 (H = X @ W16)  ||  scatter A  (independent halves)
    k_spmm1_scatter_a<<<SPMM1_BLKS + SCAT_BLKS, 256>>>(adj_rows, adj_cols,
                                                       adj_vals, h_ptr);

    // 4. SpMM2 + ReLU: out = relu(A @ H)
    {
        long long threads = (long long)(NN / 2) * 32;
        int blocks = (int)((threads + 255) / 256);
        k_spmm2<<<blocks, 256>>>(h_ptr, out);
    }
}

// round 13
// speedup vs baseline: 2.0850x; 1.0928x over previous
#include <cuda_runtime.h>
#include <cuda_fp16.h>
#include <cstdint>
#include <cstring>

// Problem constants (fixed by the reference)
#define NN      100000
#define D_IN    256
#define D_OUT   128
#define NNZ_X   3200000
#define NNZ_A   3200000
#define INV_KEEP 1.1111112f   // float32(1/0.9), matching JAX

#define CAP     96            // bucket capacity per row; P(Poisson(32) > 96) ~ 1e-20

#define SCAT_BLKS   (NNZ_X / 4 / 256)      // 3125 blocks, 4 nnz/thread
#define SPMM1_BLKS  (NN / 16)              // 6250 blocks, 16 rows per block (8 warps x 2)

// ---------------------------------------------------------------------------
// Static scratch (no allocations allowed). +8 entry tail pad: the pipelined
// gather loops prefetch up to 2 entries past a row's CAP region.
// ---------------------------------------------------------------------------
__device__ __half g_h[(size_t)NN * D_OUT];          // 25.6 MB  H = X@W (fp16)
__device__ __half g_w16[D_IN * D_OUT];              // 64 KB    W in fp16
__device__ int    g_fill[2 * NN];                   // fillX | fillA
__device__ int2   g_bktX[(size_t)NN * CAP + 8];     // 76.8 MB (col, val-bits)
__device__ int2   g_bktA[(size_t)NN * CAP + 8];     // 76.8 MB

// bit-cast helpers
__device__ __forceinline__ uint32_t h2_to_u32(half2 h) {
    uint32_t u; memcpy(&u, &h, 4); return u;
}
__device__ __forceinline__ half2 u32_to_h2(uint32_t u) {
    half2 h; memcpy(&h, &u, 4); return h;
}

// ---------------------------------------------------------------------------
// threefry2x32, key = seed(42), partitionable mode: in = (0, i), out = o0^o1
// ---------------------------------------------------------------------------
__device__ __forceinline__ uint32_t rotl32(uint32_t v, int d) {
    return (v << d) | (v >> (32 - d));
}

__device__ __forceinline__ uint32_t threefry_bits_k42(uint32_t idx) {
    const uint32_t ks1 = 42u;
    const uint32_t ks2 = 42u ^ 0x1BD11BDAu;
    uint32_t x0 = 0u;
    uint32_t x1 = idx + ks1;
#define TF_ROUND(r) { x0 += x1; x1 = rotl32(x1, r); x1 ^= x0; }
    TF_ROUND(13) TF_ROUND(15) TF_ROUND(26) TF_ROUND(6)
    x0 += ks1; x1 += ks2 + 1u;
    TF_ROUND(17) TF_ROUND(29) TF_ROUND(16) TF_ROUND(24)
    x0 += ks2; x1 += 0u + 2u;
    TF_ROUND(13) TF_ROUND(15) TF_ROUND(26) TF_ROUND(6)
    x0 += 0u; x1 += ks1 + 3u;
    TF_ROUND(17) TF_ROUND(29) TF_ROUND(16) TF_ROUND(24)
    x0 += ks1; x1 += ks2 + 4u;
    TF_ROUND(13) TF_ROUND(15) TF_ROUND(26) TF_ROUND(6)
    x0 += ks2; x1 += 0u + 5u;
#undef TF_ROUND
    return x0 ^ x1;
}

__device__ __forceinline__ float bits_to_uniform(uint32_t bits) {
    return __uint_as_float((bits >> 9) | 0x3f800000u) - 1.0f;
}

// ---------------------------------------------------------------------------
// Prep: zero fill counters (2*NN ints = 50000 int4) + convert W to fp16
// ---------------------------------------------------------------------------
#define FILL_I4  (2 * NN / 4)                 // 50000
#define WCONV    (D_IN * D_OUT / 2)           // 16384 half2 outputs

__global__ void k_prep(const float* __restrict__ W) {
    int i = blockIdx.x * blockDim.x + threadIdx.x;
    if (i < FILL_I4) {
        ((int4*)g_fill)[i] = make_int4(0, 0, 0, 0);
    } else if (i < FILL_I4 + WCONV) {
        int j = i - FILL_I4;                   // half2 index
        float2 f = ((const float2*)W)[j];
        ((half2*)g_w16)[j] = __floats2half2_rn(f.x, f.y);
    }
}

// ---------------------------------------------------------------------------
// Scatter X into row buckets, 4 nnz per thread, dropout fused
// ---------------------------------------------------------------------------
__global__ void k_scatter_x(const int* __restrict__ x_rows,
                            const int* __restrict__ x_cols,
                            const float* __restrict__ x_vals) {
    int i = (blockIdx.x * blockDim.x + threadIdx.x) * 4;
    if (i >= NNZ_X) return;
    int4   r4 = __ldg((const int4*)(x_rows + i));
    int4   c4 = __ldg((const int4*)(x_cols + i));
    float4 v4 = __ldg((const float4*)(x_vals + i));
    #pragma unroll
    for (int k = 0; k < 4; k++) {
        int   r = (&r4.x)[k];
        int   c = (&c4.x)[k];
        float v = (&v4.x)[k];
        uint32_t bits = threefry_bits_k42((uint32_t)(i + k));
        float u = bits_to_uniform(bits);
        if (0.9f + u < 1.0f) continue;     // dropped, skip entirely
        int slot = atomicAdd(g_fill + r, 1);
        if (slot < CAP)
            g_bktX[(size_t)r * CAP + slot] =
                make_int2(c, __float_as_int(v * INV_KEEP));
    }
}

// ---------------------------------------------------------------------------
// fma of 8 halves (uint4) scaled by v into 8-float accumulator
// ---------------------------------------------------------------------------
__device__ __forceinline__ void fma_h16(float4& a0, float4& a1, float v, uint4 q) {
    float2 f0 = __half22float2(u32_to_h2(q.x));
    float2 f1 = __half22float2(u32_to_h2(q.y));
    float2 f2 = __half22float2(u32_to_h2(q.z));
    float2 f3 = __half22float2(u32_to_h2(q.w));
    a0.x = fmaf(v, f0.x, a0.x); a0.y = fmaf(v, f0.y, a0.y);
    a0.z = fmaf(v, f1.x, a0.z); a0.w = fmaf(v, f1.y, a0.w);
    a1.x = fmaf(v, f2.x, a1.x); a1.y = fmaf(v, f2.y, a1.y);
    a1.z = fmaf(v, f3.x, a1.z); a1.w = fmaf(v, f3.y, a1.w);
}

// ---------------------------------------------------------------------------
// Fused launch with INTERLEAVED roles: of every 3 consecutive blocks, 2 run
// SpMM1 and 1 runs scatterA, so both kinds coexist in every scheduling wave
// (a contiguous range split serializes across waves — measured in R12).
// ---------------------------------------------------------------------------
__global__ void k_spmm1_scatter_a(const int* __restrict__ a_rows,
                                  const int* __restrict__ a_cols,
                                  const float* __restrict__ a_vals,
                                  __half* __restrict__ H) {
    int b = blockIdx.x;
    int grp = b / 3;
    int rem = b - grp * 3;
    if (rem != 2) {
        // SpMM1 block index: 2 per group
        int sb = grp * 2 + rem;                  // < SPMM1_BLKS
        int lane = threadIdx.x & 31;
        int sub = lane >> 4;              // 0/1: which row of the pair
        int sl  = lane & 15;              // lane-within-row, owns cols [sl*8, sl*8+8)
        int row = sb * 16 + (threadIdx.x >> 5) * 2 + sub;
        int n = __ldg(g_fill + row);
        if (n > CAP) n = CAP;
        const int2*  bkt = g_bktX + (size_t)row * CAP;
        const int4*  b4  = (const int4*)bkt;                 // pair of entries
        const uint4* W4  = (const uint4*)g_w16;              // 8 halves per uint4
        float4 a0 = make_float4(0.f, 0.f, 0.f, 0.f);
        float4 a1 = make_float4(0.f, 0.f, 0.f, 0.f);
        int j = 0;
        if (j + 3 < n) {
            int4 pA = __ldg(b4);
            int4 pB = __ldg(b4 + 1);
            for (; j + 3 < n; j += 4) {
                int kn = (j >> 1) + 2;
                int4 pA2 = __ldg(b4 + kn);   // may overread into pad: unused then
                int4 pB2 = __ldg(b4 + kn + 1);
                uint4 q0 = __ldg(W4 + (size_t)pA.x * 16 + sl);
                uint4 q1 = __ldg(W4 + (size_t)pA.z * 16 + sl);
                uint4 q2 = __ldg(W4 + (size_t)pB.x * 16 + sl);
                uint4 q3 = __ldg(W4 + (size_t)pB.z * 16 + sl);
                fma_h16(a0, a1, __int_as_float(pA.y), q0);
                fma_h16(a0, a1, __int_as_float(pA.w), q1);
                fma_h16(a0, a1, __int_as_float(pB.y), q2);
                fma_h16(a0, a1, __int_as_float(pB.w), q3);
                pA = pA2; pB = pB2;
            }
        }
        for (; j < n; j++) {
            int2 cv = __ldg(bkt + j);
            uint4 q = __ldg(W4 + (size_t)cv.x * 16 + sl);
            fma_h16(a0, a1, __int_as_float(cv.y), q);
        }
        uint4 packed;
        packed.x = h2_to_u32(__floats2half2_rn(a0.x, a0.y));
        packed.y = h2_to_u32(__floats2half2_rn(a0.z, a0.w));
        packed.z = h2_to_u32(__floats2half2_rn(a1.x, a1.y));
        packed.w = h2_to_u32(__floats2half2_rn(a1.z, a1.w));
        ((uint4*)H)[(size_t)row * 16 + sl] = packed;
    } else {
        // scatterA block index: 1 per group
        int i = (grp * 256 + threadIdx.x) * 4;
        if (i >= NNZ_A) return;
        int4   r4 = __ldg((const int4*)(a_rows + i));
        int4   c4 = __ldg((const int4*)(a_cols + i));
        float4 v4 = __ldg((const float4*)(a_vals + i));
        #pragma unroll
        for (int k = 0; k < 4; k++) {
            int   r = (&r4.x)[k];
            int   c = (&c4.x)[k];
            float v = (&v4.x)[k];
            int slot = atomicAdd(g_fill + NN + r, 1);
            if (slot < CAP)
                g_bktA[(size_t)r * CAP + slot] = make_int2(c, __float_as_int(v));
        }
    }
}

// ---------------------------------------------------------------------------
// SpMM2 + ReLU: out(fp32) = relu(A @ H).  2 rows/warp, pipelined unroll 4.
// ---------------------------------------------------------------------------
__global__ void k_spmm2(const __half* __restrict__ H, float* __restrict__ out) {
    int gw = (blockIdx.x * blockDim.x + threadIdx.x) >> 5;
    int lane = threadIdx.x & 31;
    int sub = lane >> 4;
    int sl  = lane & 15;
    int row = gw * 2 + sub;
    if (row >= NN) return;
    int n = __ldg(g_fill + NN + row);
    if (n > CAP) n = CAP;
    const int2*  bkt = g_bktA + (size_t)row * CAP;
    const int4*  b4  = (const int4*)bkt;
    const uint4* H4  = (const uint4*)H;
    float4 a0 = make_float4(0.f, 0.f, 0.f, 0.f);
    float4 a1 = make_float4(0.f, 0.f, 0.f, 0.f);
    int j = 0;
    if (j + 3 < n) {
        int4 pA = __ldg(b4);
        int4 pB = __ldg(b4 + 1);
        for (; j + 3 < n; j += 4) {
            int kn = (j >> 1) + 2;
            int4 pA2 = __ldg(b4 + kn);       // prefetch next iteration's entries
            int4 pB2 = __ldg(b4 + kn + 1);
            uint4 q0 = __ldg(H4 + (size_t)pA.x * 16 + sl);
            uint4 q1 = __ldg(H4 + (size_t)pA.z * 16 + sl);
            uint4 q2 = __ldg(H4 + (size_t)pB.x * 16 + sl);
            uint4 q3 = __ldg(H4 + (size_t)pB.z * 16 + sl);
            fma_h16(a0, a1, __int_as_float(pA.y), q0);
            fma_h16(a0, a1, __int_as_float(pA.w), q1);
            fma_h16(a0, a1, __int_as_float(pB.y), q2);
            fma_h16(a0, a1, __int_as_float(pB.w), q3);
            pA = pA2; pB = pB2;
        }
    }
    for (; j < n; j++) {
        int2 cv = __ldg(bkt + j);
        uint4 q = __ldg(H4 + (size_t)cv.x * 16 + sl);
        fma_h16(a0, a1, __int_as_float(cv.y), q);
    }
    a0.x = fmaxf(a0.x, 0.f); a0.y = fmaxf(a0.y, 0.f);
    a0.z = fmaxf(a0.z, 0.f); a0.w = fmaxf(a0.w, 0.f);
    a1.x = fmaxf(a1.x, 0.f); a1.y = fmaxf(a1.y, 0.f);
    a1.z = fmaxf(a1.z, 0.f); a1.w = fmaxf(a1.w, 0.f);
    float4* o4 = (float4*)out + (size_t)row * 32 + sl * 2;   // 8 floats = 2x float4
    o4[0] = a0;
    o4[1] = a1;
}

// ---------------------------------------------------------------------------
// Launch: 4 kernels; scatterA interleaved with spmm1 inside one launch
// ---------------------------------------------------------------------------
extern "C" void kernel_launch(void* const* d_in, const int* in_sizes, int n_in,
                              void* d_out, int out_size) {
    const int*   x_rows   = (const int*)  d_in[0];
    const int*   x_cols   = (const int*)  d_in[1];
    const float* x_vals   = (const float*)d_in[2];
    const int*   adj_rows = (const int*)  d_in[3];
    const int*   adj_cols = (const int*)  d_in[4];
    const float* adj_vals = (const float*)d_in[5];
    const float* W        = (const float*)d_in[6];
    float* out = (float*)d_out;

    __half* h_ptr;  cudaGetSymbolAddress((void**)&h_ptr, g_h);

    // 1. zero fill counters + convert W to fp16
    {
        int work = FILL_I4 + WCONV;
        k_prep<<<(work + 255) / 256, 256>>>(W);
    }

    // 2. scatter X into row buckets (dropout fused)
    k_scatter_x<<<SCAT_BLKS, 256>>>(x_rows, x_cols, x_vals);

    // 3. fused + interleaved: SpMM1 (2 of 3 blocks) || scatterA (1 of 3 blocks)
    k_spmm1_scatter_a<<<SPMM1_BLKS + SCAT_BLKS, 256>>>(adj_rows, adj_cols,
                                                       adj_vals, h_ptr);

    // 4. SpMM2 + ReLU: out = relu(A @ H)
    {
        long long threads = (long long)(NN / 2) * 32;
        int blocks = (int)((threads + 255) / 256);
        k_spmm2<<<blocks, 256>>>(h_ptr, out);
    }
}